// round 7
// baseline (speedup 1.0000x reference)
#include <cuda_runtime.h>
#include <cuda_bf16.h>
#include <cstdint>

// ---------------------------------------------------------------------------
// LocalAttention on GB300 (compute_103-safe: NO tcgen05 — ptxas rejects 'a'
// features on this bench's PTX target; use sm_80-class HMMA mma.sync instead):
//   qkv = x@w_in^T + b_in           -> bf16-split (3-term) mma.sync GEMM
//   banded causal attention (W=128) -> fp32 FFMA2 flash kernel
//   out = attn@w_out^T + b_out      -> bf16-split mma.sync GEMM
// B=4 S=2048 E=1024 H=16 HD=64 W=128
// ---------------------------------------------------------------------------

#define Bn   4
#define Sn   2048
#define En   1024
#define Hn   16
#define HDn  64
#define Wn   128
#define Kdim 1024

// ============================ small PTX helpers ============================
typedef unsigned long long f32x2_t;

__device__ __forceinline__ f32x2_t ffma2(f32x2_t a, f32x2_t b, f32x2_t c) {
    f32x2_t d; asm("fma.rn.f32x2 %0, %1, %2, %3;" : "=l"(d) : "l"(a), "l"(b), "l"(c)); return d;
}
__device__ __forceinline__ f32x2_t fadd2(f32x2_t a, f32x2_t b) {
    f32x2_t d; asm("add.rn.f32x2 %0, %1, %2;" : "=l"(d) : "l"(a), "l"(b)); return d;
}
__device__ __forceinline__ f32x2_t pack2(float lo, float hi) {
    f32x2_t d; asm("mov.b64 %0, {%1, %2};" : "=l"(d) : "f"(lo), "f"(hi)); return d;
}
__device__ __forceinline__ void unpack2(f32x2_t v, float& lo, float& hi) {
    asm("mov.b64 {%0, %1}, %2;" : "=f"(lo), "=f"(hi) : "l"(v));
}
__device__ __forceinline__ uint32_t smem_u32(const void* p) {
    uint32_t a; asm("{ .reg .u64 t; cvta.to.shared.u64 t, %1; cvt.u32.u64 %0, t; }" : "=r"(a) : "l"(p));
    return a;
}
__device__ __forceinline__ uint32_t lds32(uint32_t addr) {
    uint32_t v; asm volatile("ld.shared.b32 %0, [%1];" : "=r"(v) : "r"(addr)); return v;
}
__device__ __forceinline__ void cp16(uint32_t saddr, const void* gaddr) {
    asm volatile("cp.async.cg.shared.global [%0], [%1], 16;" :: "r"(saddr), "l"(gaddr) : "memory");
}
__device__ __forceinline__ void cp_commit() {
    asm volatile("cp.async.commit_group;" ::: "memory");
}

// bf16 HMMA: D(16x8,f32) += A(16x16,bf16,row) * B(16x8,bf16,col)
__device__ __forceinline__ void mma_bf16(float* d, const uint32_t* a, uint32_t b0, uint32_t b1) {
    asm volatile(
        "mma.sync.aligned.m16n8k16.row.col.f32.bf16.bf16.f32 "
        "{%0,%1,%2,%3}, {%4,%5,%6,%7}, {%8,%9}, {%0,%1,%2,%3};"
        : "+f"(d[0]), "+f"(d[1]), "+f"(d[2]), "+f"(d[3])
        : "r"(a[0]), "r"(a[1]), "r"(a[2]), "r"(a[3]), "r"(b0), "r"(b1));
}

// ============================== scratch =====================================
__device__ float          g_qkv[(size_t)Bn * Sn * 3 * En];      // fp32 [8192,3072]
__device__ __nv_bfloat16  g_xhi[(size_t)Bn * Sn * En];
__device__ __nv_bfloat16  g_xlo[(size_t)Bn * Sn * En];
__device__ __nv_bfloat16  g_winhi[(size_t)3 * En * En];
__device__ __nv_bfloat16  g_winlo[(size_t)3 * En * En];
__device__ __nv_bfloat16  g_wouthi[(size_t)En * En];
__device__ __nv_bfloat16  g_woutlo[(size_t)En * En];
__device__ __nv_bfloat16  g_ahi[(size_t)Bn * Sn * En];
__device__ __nv_bfloat16  g_alo[(size_t)Bn * Sn * En];

// ========================= fp32 -> bf16 hi/lo split =========================
__global__ void __launch_bounds__(256)
conv_hilo(const float4* __restrict__ src, uint2* __restrict__ hi, uint2* __restrict__ lo, int n4)
{
    int i = blockIdx.x * 256 + threadIdx.x;
    if (i >= n4) return;
    float4 v = src[i];
    __nv_bfloat16 h0 = __float2bfloat16_rn(v.x), h1 = __float2bfloat16_rn(v.y);
    __nv_bfloat16 h2 = __float2bfloat16_rn(v.z), h3 = __float2bfloat16_rn(v.w);
    __nv_bfloat16 l0 = __float2bfloat16_rn(v.x - __bfloat162float(h0));
    __nv_bfloat16 l1 = __float2bfloat16_rn(v.y - __bfloat162float(h1));
    __nv_bfloat16 l2 = __float2bfloat16_rn(v.z - __bfloat162float(h2));
    __nv_bfloat16 l3 = __float2bfloat16_rn(v.w - __bfloat162float(h3));
    uint2 ph, pl;
    ph.x = ((uint32_t)__bfloat16_as_ushort(h1) << 16) | __bfloat16_as_ushort(h0);
    ph.y = ((uint32_t)__bfloat16_as_ushort(h3) << 16) | __bfloat16_as_ushort(h2);
    pl.x = ((uint32_t)__bfloat16_as_ushort(l1) << 16) | __bfloat16_as_ushort(l0);
    pl.y = ((uint32_t)__bfloat16_as_ushort(l3) << 16) | __bfloat16_as_ushort(l2);
    hi[i] = ph;
    lo[i] = pl;
}

// ================== bf16-split NT GEMM on HMMA (mma.sync) ===================
// C[m,n] = sum_k (Ahi+Alo)[m,k]*(Bhi+Blo)[n,k] + bias[n], dropping lo*lo.
// CTA tile 128x128; 8 warps (2 m x 4 n), warp tile 64x32; K chunks of 32.
// Double-buffered cp.async; smem rows padded to 80 B (conflict-free frags).
#define MT 128
#define NT 128
#define KC 32
#define NCH (Kdim / KC)              // 32

#define SROW   80                    // bytes per 32-bf16 row (64 data + 16 pad)
#define TSZ    (128 * SROW)          // 10240 B per half-tile
#define T_AHI  0
#define T_ALO  (1 * TSZ)
#define T_BHI  (2 * TSZ)
#define T_BLO  (3 * TSZ)
#define STAGE  (4 * TSZ)             // 40960 B
#define GEMM_SMEM (2 * STAGE)        // 81920 B

__global__ void __launch_bounds__(256)
gemm_bf16split(const __nv_bfloat16* __restrict__ Ahi, const __nv_bfloat16* __restrict__ Alo,
               const __nv_bfloat16* __restrict__ Bhi, const __nv_bfloat16* __restrict__ Blo,
               const float* __restrict__ bias, float* __restrict__ C, int N)
{
    extern __shared__ __align__(16) char dsm[];
    const uint32_t base = smem_u32(dsm);

    const int tid  = threadIdx.x;
    const int wid  = tid >> 5;
    const int lane = tid & 31;
    const int wm   = wid & 1;          // 0..1 -> m offset 0/64
    const int wn   = wid >> 1;         // 0..3 -> n offset 0/32/64/96
    const int g    = lane >> 2;        // 0..7
    const int tig  = lane & 3;         // 0..3
    const int m0 = blockIdx.y * MT;
    const int n0 = blockIdx.x * NT;

    // cp.async mapping: item = tid + j*256 (0..511) -> row = item>>2, w16 = item&3
    const int ldr = tid >> 2;          // base row for j=0
    const int ldw = tid & 3;           // 16B word in row

    float d[4][4][4];
#pragma unroll
    for (int mt = 0; mt < 4; ++mt)
#pragma unroll
        for (int nt = 0; nt < 4; ++nt)
#pragma unroll
            for (int q = 0; q < 4; ++q) d[mt][nt][q] = 0.0f;

    auto load_stage = [&](int c, int s) {
        const uint32_t sb = base + (uint32_t)s * STAGE;
        const int kOff = c * KC + ldw * 8;     // bf16 element offset in K
#pragma unroll
        for (int j = 0; j < 2; ++j) {
            const int row = ldr + j * 64;
            const uint32_t so = (uint32_t)row * SROW + (uint32_t)ldw * 16;
            const size_t ga = (size_t)(m0 + row) * Kdim + kOff;
            const size_t gb = (size_t)(n0 + row) * Kdim + kOff;
            cp16(sb + T_AHI + so, Ahi + ga);
            cp16(sb + T_ALO + so, Alo + ga);
            cp16(sb + T_BHI + so, Bhi + gb);
            cp16(sb + T_BLO + so, Blo + gb);
        }
        cp_commit();
    };

    load_stage(0, 0);
    load_stage(1, 1);

    for (int c = 0; c < NCH; ++c) {
        const int s = c & 1;
        if (c + 2 < NCH) asm volatile("cp.async.wait_group 1;" ::: "memory");
        else             asm volatile("cp.async.wait_group 0;" ::: "memory");
        __syncthreads();

        const uint32_t sb = base + (uint32_t)s * STAGE;
#pragma unroll
        for (int ks = 0; ks < 2; ++ks) {
            const uint32_t kB = (uint32_t)((ks * 16 + tig * 2) * 2);  // byte offset in row
            uint32_t ah[4][4], al[4][4];
#pragma unroll
            for (int mt = 0; mt < 4; ++mt) {
                const uint32_t r0 = (uint32_t)(wm * 64 + mt * 16 + g) * SROW + kB;
                ah[mt][0] = lds32(sb + T_AHI + r0);
                ah[mt][1] = lds32(sb + T_AHI + r0 + 8 * SROW);
                ah[mt][2] = lds32(sb + T_AHI + r0 + 16);
                ah[mt][3] = lds32(sb + T_AHI + r0 + 8 * SROW + 16);
                al[mt][0] = lds32(sb + T_ALO + r0);
                al[mt][1] = lds32(sb + T_ALO + r0 + 8 * SROW);
                al[mt][2] = lds32(sb + T_ALO + r0 + 16);
                al[mt][3] = lds32(sb + T_ALO + r0 + 8 * SROW + 16);
            }
#pragma unroll
            for (int nt = 0; nt < 4; ++nt) {
                const uint32_t rb = (uint32_t)(wn * 32 + nt * 8 + g) * SROW + kB;
                const uint32_t bh0 = lds32(sb + T_BHI + rb);
                const uint32_t bh1 = lds32(sb + T_BHI + rb + 16);
                const uint32_t bl0 = lds32(sb + T_BLO + rb);
                const uint32_t bl1 = lds32(sb + T_BLO + rb + 16);
#pragma unroll
                for (int mt = 0; mt < 4; ++mt) {
                    mma_bf16(d[mt][nt], ah[mt], bh0, bh1);   // hi*hi
                    mma_bf16(d[mt][nt], ah[mt], bl0, bl1);   // hi*lo
                    mma_bf16(d[mt][nt], al[mt], bh0, bh1);   // lo*hi
                }
            }
        }
        __syncthreads();
        if (c + 2 < NCH) load_stage(c + 2, s);
    }

    // epilogue: add bias, write fp32
#pragma unroll
    for (int nt = 0; nt < 4; ++nt) {
        const int col = n0 + wn * 32 + nt * 8 + tig * 2;
        const float2 bv = *(const float2*)(bias + col);
#pragma unroll
        for (int mt = 0; mt < 4; ++mt) {
            const int row = m0 + wm * 64 + mt * 16 + g;
            float2 v0 = make_float2(d[mt][nt][0] + bv.x, d[mt][nt][1] + bv.y);
            float2 v1 = make_float2(d[mt][nt][2] + bv.x, d[mt][nt][3] + bv.y);
            *(float2*)(C + (size_t)row * N + col)       = v0;
            *(float2*)(C + (size_t)(row + 8) * N + col) = v1;
        }
    }
}

// ===================== banded causal attention (fp32) =======================
// row i attends to cols [i-W, i]; one thread per query; K/V streamed via smem.
// Writes output directly as bf16 hi/lo split for the second GEMM.
__global__ void __launch_bounds__(128)
attn_kernel(const float* __restrict__ qkv,
            __nv_bfloat16* __restrict__ ohi, __nv_bfloat16* __restrict__ olo)
{
    __shared__ __align__(16) float Ks[64][HDn];
    __shared__ __align__(16) float Vs[64][HDn];

    const int qtile = blockIdx.x;
    const int h     = blockIdx.y;
    const int b     = blockIdx.z;
    const int qbase = qtile * 128;
    const int gq    = qbase + threadIdx.x;
    const int kstart = (qbase - Wn) > 0 ? (qbase - Wn) : 0;
    const int span   = qbase + 128 - kstart;
    const float scale = 0.125f;

    f32x2_t q2[32];
    {
        const f32x2_t* qp = (const f32x2_t*)(qkv + (size_t)(b * Sn + gq) * (3 * En) + h * HDn);
#pragma unroll
        for (int i = 0; i < 32; i++) q2[i] = qp[i];
    }

    f32x2_t acc2[32];
#pragma unroll
    for (int i = 0; i < 32; i++) acc2[i] = 0ULL;
    float m = -3.0e38f, l = 0.0f;

    for (int c0 = 0; c0 < span; c0 += 64) {
        const int nk = (span - c0) < 64 ? (span - c0) : 64;
        __syncthreads();
        for (int idx = threadIdx.x; idx < 64 * 16; idx += 128) {
            int r = idx >> 4, c4 = (idx & 15) << 2;
            if (r < nk) {
                const float* src =
                    qkv + (size_t)(b * Sn + kstart + c0 + r) * (3 * En) + h * HDn + c4;
                *(float4*)&Ks[r][c4] = *(const float4*)(src + En);
                *(float4*)&Vs[r][c4] = *(const float4*)(src + 2 * En);
            }
        }
        __syncthreads();

        for (int j = 0; j < nk; ++j) {
            const f32x2_t* kp = (const f32x2_t*)&Ks[j][0];
            f32x2_t s0 = 0ULL, s1 = 0ULL, s2 = 0ULL, s3 = 0ULL;
#pragma unroll
            for (int i = 0; i < 32; i += 4) {
                s0 = ffma2(q2[i + 0], kp[i + 0], s0);
                s1 = ffma2(q2[i + 1], kp[i + 1], s1);
                s2 = ffma2(q2[i + 2], kp[i + 2], s2);
                s3 = ffma2(q2[i + 3], kp[i + 3], s3);
            }
            s0 = fadd2(fadd2(s0, s1), fadd2(s2, s3));
            float slo, shi; unpack2(s0, slo, shi);
            float s = (slo + shi) * scale;

            const int gj = kstart + c0 + j;
            if (gj <= gq && gj >= gq - Wn) {
                const f32x2_t* vp = (const f32x2_t*)&Vs[j][0];
                if (s <= m) {
                    float p = __expf(s - m);
                    l += p;
                    f32x2_t p2 = pack2(p, p);
#pragma unroll
                    for (int i = 0; i < 32; i++) acc2[i] = ffma2(p2, vp[i], acc2[i]);
                } else {
                    float corr = __expf(m - s);
                    m = s;
                    l = l * corr + 1.0f;
                    f32x2_t c2v = pack2(corr, corr);
#pragma unroll
                    for (int i = 0; i < 32; i++) acc2[i] = ffma2(acc2[i], c2v, vp[i]);
                }
            }
        }
    }

    const float inv = 1.0f / l;
    const size_t rb = (size_t)(b * Sn + gq) * En + h * HDn;
    uint32_t* hp = (uint32_t*)(ohi + rb);
    uint32_t* lp = (uint32_t*)(olo + rb);
#pragma unroll
    for (int i = 0; i < 32; i++) {
        float v0, v1; unpack2(acc2[i], v0, v1);
        v0 *= inv; v1 *= inv;
        __nv_bfloat16 h0 = __float2bfloat16_rn(v0), h1 = __float2bfloat16_rn(v1);
        __nv_bfloat16 l0 = __float2bfloat16_rn(v0 - __bfloat162float(h0));
        __nv_bfloat16 l1 = __float2bfloat16_rn(v1 - __bfloat162float(h1));
        hp[i] = ((uint32_t)__bfloat16_as_ushort(h1) << 16) | __bfloat16_as_ushort(h0);
        lp[i] = ((uint32_t)__bfloat16_as_ushort(l1) << 16) | __bfloat16_as_ushort(l0);
    }
}

// ---------------------------------------------------------------------------
extern "C" void kernel_launch(void* const* d_in, const int* in_sizes, int n_in,
                              void* d_out, int out_size)
{
    const float *x = 0, *w_in = 0, *b_in = 0, *w_out = 0, *b_out = 0;
    for (int i = 0; i < n_in; i++) {
        const float* p = (const float*)d_in[i];
        switch (in_sizes[i]) {
            case Bn * Sn * En: x     = p; break;
            case 3 * En * En:  w_in  = p; break;
            case 3 * En:       b_in  = p; break;
            case En * En:      w_out = p; break;
            case En:           b_out = p; break;
            default: break;
        }
    }

    void *p_qkv, *p_xhi, *p_xlo, *p_winhi, *p_winlo, *p_wouthi, *p_woutlo, *p_ahi, *p_alo;
    cudaGetSymbolAddress(&p_qkv, g_qkv);
    cudaGetSymbolAddress(&p_xhi, g_xhi);     cudaGetSymbolAddress(&p_xlo, g_xlo);
    cudaGetSymbolAddress(&p_winhi, g_winhi); cudaGetSymbolAddress(&p_winlo, g_winlo);
    cudaGetSymbolAddress(&p_wouthi, g_wouthi); cudaGetSymbolAddress(&p_woutlo, g_woutlo);
    cudaGetSymbolAddress(&p_ahi, g_ahi);     cudaGetSymbolAddress(&p_alo, g_alo);

    cudaFuncSetAttribute(gemm_bf16split, cudaFuncAttributeMaxDynamicSharedMemorySize, GEMM_SMEM);

    // fp32 -> bf16 hi/lo splits
    conv_hilo<<<8192, 256>>>((const float4*)x,
                             (uint2*)p_xhi, (uint2*)p_xlo, (Bn * Sn * En) / 4);
    conv_hilo<<<3072, 256>>>((const float4*)w_in,
                             (uint2*)p_winhi, (uint2*)p_winlo, (3 * En * En) / 4);
    conv_hilo<<<1024, 256>>>((const float4*)w_out,
                             (uint2*)p_wouthi, (uint2*)p_woutlo, (En * En) / 4);

    // 1) QKV projection: [8192,1024] x [3072,1024]^T -> fp32 qkv
    {
        dim3 g((3 * En) / NT, (Bn * Sn) / MT);   // 24 x 64
        gemm_bf16split<<<g, 256, GEMM_SMEM>>>(
            (const __nv_bfloat16*)p_xhi, (const __nv_bfloat16*)p_xlo,
            (const __nv_bfloat16*)p_winhi, (const __nv_bfloat16*)p_winlo,
            b_in, (float*)p_qkv, 3 * En);
    }

    // 2) banded attention (fp32 in, bf16 hi/lo out)
    {
        dim3 g(Sn / 128, Hn, Bn);
        attn_kernel<<<g, 128>>>((const float*)p_qkv,
                                (__nv_bfloat16*)p_ahi, (__nv_bfloat16*)p_alo);
    }

    // 3) output projection: [8192,1024] x [1024,1024]^T -> d_out
    {
        dim3 g(En / NT, (Bn * Sn) / MT);         // 8 x 64
        gemm_bf16split<<<g, 256, GEMM_SMEM>>>(
            (const __nv_bfloat16*)p_ahi, (const __nv_bfloat16*)p_alo,
            (const __nv_bfloat16*)p_wouthi, (const __nv_bfloat16*)p_woutlo,
            b_out, (float*)d_out, En);
    }
}

// round 8
// speedup vs baseline: 1.3646x; 1.3646x over previous
#include <cuda_runtime.h>
#include <cuda_bf16.h>
#include <cstdint>

// ---------------------------------------------------------------------------
// LocalAttention on GB300 (compute_103-safe: no tcgen05 'a' features):
//   qkv = x@w_in^T + b_in           -> bf16-split (3-term) HMMA GEMM (ldmatrix)
//   banded causal attention (W=128) -> fp32 FFMA2 flash kernel (warp-clamped)
//   out = attn@w_out^T + b_out      -> bf16-split HMMA GEMM
// B=4 S=2048 E=1024 H=16 HD=64 W=128
// ---------------------------------------------------------------------------

#define Bn   4
#define Sn   2048
#define En   1024
#define Hn   16
#define HDn  64
#define Wn   128
#define Kdim 1024

// ============================ small PTX helpers ============================
typedef unsigned long long f32x2_t;

__device__ __forceinline__ f32x2_t ffma2(f32x2_t a, f32x2_t b, f32x2_t c) {
    f32x2_t d; asm("fma.rn.f32x2 %0, %1, %2, %3;" : "=l"(d) : "l"(a), "l"(b), "l"(c)); return d;
}
__device__ __forceinline__ f32x2_t fadd2(f32x2_t a, f32x2_t b) {
    f32x2_t d; asm("add.rn.f32x2 %0, %1, %2;" : "=l"(d) : "l"(a), "l"(b)); return d;
}
__device__ __forceinline__ f32x2_t pack2(float lo, float hi) {
    f32x2_t d; asm("mov.b64 %0, {%1, %2};" : "=l"(d) : "f"(lo), "f"(hi)); return d;
}
__device__ __forceinline__ void unpack2(f32x2_t v, float& lo, float& hi) {
    asm("mov.b64 {%0, %1}, %2;" : "=f"(lo), "=f"(hi) : "l"(v));
}
__device__ __forceinline__ uint32_t smem_u32(const void* p) {
    uint32_t a; asm("{ .reg .u64 t; cvta.to.shared.u64 t, %1; cvt.u32.u64 %0, t; }" : "=r"(a) : "l"(p));
    return a;
}
__device__ __forceinline__ void cp16(uint32_t saddr, const void* gaddr) {
    asm volatile("cp.async.cg.shared.global [%0], [%1], 16;" :: "r"(saddr), "l"(gaddr) : "memory");
}
__device__ __forceinline__ void cp_commit() {
    asm volatile("cp.async.commit_group;" ::: "memory");
}
__device__ __forceinline__ void ldsm4(uint32_t* r, uint32_t a) {
    asm volatile("ldmatrix.sync.aligned.m8n8.x4.shared.b16 {%0,%1,%2,%3}, [%4];"
                 : "=r"(r[0]), "=r"(r[1]), "=r"(r[2]), "=r"(r[3]) : "r"(a));
}
__device__ __forceinline__ void ldsm2(uint32_t& r0, uint32_t& r1, uint32_t a) {
    asm volatile("ldmatrix.sync.aligned.m8n8.x2.shared.b16 {%0,%1}, [%2];"
                 : "=r"(r0), "=r"(r1) : "r"(a));
}

// bf16 HMMA: D(16x8,f32) += A(16x16,bf16,row) * B(16x8,bf16,col)
__device__ __forceinline__ void mma_bf16(float* d, const uint32_t* a, uint32_t b0, uint32_t b1) {
    asm volatile(
        "mma.sync.aligned.m16n8k16.row.col.f32.bf16.bf16.f32 "
        "{%0,%1,%2,%3}, {%4,%5,%6,%7}, {%8,%9}, {%0,%1,%2,%3};"
        : "+f"(d[0]), "+f"(d[1]), "+f"(d[2]), "+f"(d[3])
        : "r"(a[0]), "r"(a[1]), "r"(a[2]), "r"(a[3]), "r"(b0), "r"(b1));
}

// ============================== scratch =====================================
__device__ float          g_qkv[(size_t)Bn * Sn * 3 * En];      // fp32 [8192,3072]
__device__ __nv_bfloat16  g_xhi[(size_t)Bn * Sn * En];
__device__ __nv_bfloat16  g_xlo[(size_t)Bn * Sn * En];
__device__ __nv_bfloat16  g_winhi[(size_t)3 * En * En];
__device__ __nv_bfloat16  g_winlo[(size_t)3 * En * En];
__device__ __nv_bfloat16  g_wouthi[(size_t)En * En];
__device__ __nv_bfloat16  g_woutlo[(size_t)En * En];
__device__ __nv_bfloat16  g_ahi[(size_t)Bn * Sn * En];
__device__ __nv_bfloat16  g_alo[(size_t)Bn * Sn * En];

// ========================= fp32 -> bf16 hi/lo split =========================
__global__ void __launch_bounds__(256)
conv_hilo(const float4* __restrict__ src, uint2* __restrict__ hi, uint2* __restrict__ lo, int n4)
{
    int i = blockIdx.x * 256 + threadIdx.x;
    if (i >= n4) return;
    float4 v = src[i];
    __nv_bfloat16 h0 = __float2bfloat16_rn(v.x), h1 = __float2bfloat16_rn(v.y);
    __nv_bfloat16 h2 = __float2bfloat16_rn(v.z), h3 = __float2bfloat16_rn(v.w);
    __nv_bfloat16 l0 = __float2bfloat16_rn(v.x - __bfloat162float(h0));
    __nv_bfloat16 l1 = __float2bfloat16_rn(v.y - __bfloat162float(h1));
    __nv_bfloat16 l2 = __float2bfloat16_rn(v.z - __bfloat162float(h2));
    __nv_bfloat16 l3 = __float2bfloat16_rn(v.w - __bfloat162float(h3));
    uint2 ph, pl;
    ph.x = ((uint32_t)__bfloat16_as_ushort(h1) << 16) | __bfloat16_as_ushort(h0);
    ph.y = ((uint32_t)__bfloat16_as_ushort(h3) << 16) | __bfloat16_as_ushort(h2);
    pl.x = ((uint32_t)__bfloat16_as_ushort(l1) << 16) | __bfloat16_as_ushort(l0);
    pl.y = ((uint32_t)__bfloat16_as_ushort(l3) << 16) | __bfloat16_as_ushort(l2);
    hi[i] = ph;
    lo[i] = pl;
}

// ================== bf16-split NT GEMM on HMMA + ldmatrix ===================
// C[m,n] = sum_k (Ahi+Alo)[m,k]*(Bhi+Blo)[n,k] + bias[n], dropping lo*lo.
// CTA tile 128x128; 8 warps (2m x 4n), warp tile 64x32; K chunks of 32 bf16.
// Rows are 64B with XOR swizzle (word ^= (row>>1)&3): conflict-free cp.async
// stores and ldmatrix reads. 32KB/stage, double-buffered => 2 CTAs/SM.
#define MT 128
#define NT 128
#define KC 32
#define NCH (Kdim / KC)              // 32

#define TSZ    (128 * 64)            // 8192 B per half-tile
#define T_AHI  0
#define T_ALO  (1 * TSZ)
#define T_BHI  (2 * TSZ)
#define T_BLO  (3 * TSZ)
#define STAGE  (4 * TSZ)             // 32768 B
#define GEMM_SMEM (2 * STAGE)        // 65536 B

__global__ void __launch_bounds__(256, 2)
gemm_bf16split(const __nv_bfloat16* __restrict__ Ahi, const __nv_bfloat16* __restrict__ Alo,
               const __nv_bfloat16* __restrict__ Bhi, const __nv_bfloat16* __restrict__ Blo,
               const float* __restrict__ bias, float* __restrict__ C, int N)
{
    extern __shared__ __align__(16) char dsm[];
    const uint32_t base = smem_u32(dsm);

    const int tid  = threadIdx.x;
    const int wid  = tid >> 5;
    const int lane = tid & 31;
    const int wm   = wid & 1;          // m offset 0/64
    const int wn   = wid >> 1;         // n offset 0/32/64/96
    const int g    = lane >> 2;        // 0..7
    const int tig  = lane & 3;         // 0..3
    const int m0 = blockIdx.y * MT;
    const int n0 = blockIdx.x * NT;

    // ldmatrix per-lane address components
    const int aRow   = wm * 64 + (lane & 15);        // + mt*16
    const int aWSel  = lane >> 4;                    // k-word parity
    const int aSw    = ((lane & 15) >> 1) & 3;
    const int bRow   = wn * 32 + (lane & 7);         // + nt*8
    const int bWSel  = (lane >> 3) & 1;
    const int bSw    = ((lane & 7) >> 1) & 3;

    float d[4][4][4];
#pragma unroll
    for (int mt = 0; mt < 4; ++mt)
#pragma unroll
        for (int nt = 0; nt < 4; ++nt)
#pragma unroll
            for (int q = 0; q < 4; ++q) d[mt][nt][q] = 0.0f;

    // cp.async mapping: item in [0,512): row=item>>2, word=item&3 (per 8KB tile)
    auto load_stage = [&](int c, int s) {
        const uint32_t sb = base + (uint32_t)s * STAGE;
#pragma unroll
        for (int j = 0; j < 2; ++j) {
            const int item = tid + j * 256;
            const int row = item >> 2, w = item & 3;
            const int pw = w ^ ((row >> 1) & 3);
            const uint32_t so = (uint32_t)(row * 64 + pw * 16);
            const int gk = c * KC + w * 8;
            const size_t ga = (size_t)(m0 + row) * Kdim + gk;
            const size_t gb = (size_t)(n0 + row) * Kdim + gk;
            cp16(sb + T_AHI + so, Ahi + ga);
            cp16(sb + T_ALO + so, Alo + ga);
            cp16(sb + T_BHI + so, Bhi + gb);
            cp16(sb + T_BLO + so, Blo + gb);
        }
        cp_commit();
    };

    load_stage(0, 0);
    load_stage(1, 1);

    for (int c = 0; c < NCH; ++c) {
        const int s = c & 1;
        if (c + 2 < NCH) asm volatile("cp.async.wait_group 1;" ::: "memory");
        else             asm volatile("cp.async.wait_group 0;" ::: "memory");
        __syncthreads();

        const uint32_t sb = base + (uint32_t)s * STAGE;
#pragma unroll
        for (int ks = 0; ks < 2; ++ks) {
            // per-lane swizzled byte offsets for this ks
            const int aPw = (ks * 2 + aWSel) ^ aSw;
            const int bPw = (ks * 2 + bWSel) ^ bSw;
            const uint32_t aOff = (uint32_t)(aRow * 64 + aPw * 16);
            const uint32_t bOff = (uint32_t)(bRow * 64 + bPw * 16);

            uint32_t af[4][4];
            // ---- pass 1: A-hi x (B-hi + B-lo) ----
#pragma unroll
            for (int mt = 0; mt < 4; ++mt)
                ldsm4(af[mt], sb + T_AHI + aOff + (uint32_t)(mt * 16 * 64));
#pragma unroll
            for (int nt = 0; nt < 4; ++nt) {
                uint32_t bh0, bh1, bl0, bl1;
                ldsm2(bh0, bh1, sb + T_BHI + bOff + (uint32_t)(nt * 8 * 64));
                ldsm2(bl0, bl1, sb + T_BLO + bOff + (uint32_t)(nt * 8 * 64));
#pragma unroll
                for (int mt = 0; mt < 4; ++mt) {
                    mma_bf16(d[mt][nt], af[mt], bh0, bh1);
                    mma_bf16(d[mt][nt], af[mt], bl0, bl1);
                }
            }
            // ---- pass 2: A-lo x B-hi ----
#pragma unroll
            for (int mt = 0; mt < 4; ++mt)
                ldsm4(af[mt], sb + T_ALO + aOff + (uint32_t)(mt * 16 * 64));
#pragma unroll
            for (int nt = 0; nt < 4; ++nt) {
                uint32_t bh0, bh1;
                ldsm2(bh0, bh1, sb + T_BHI + bOff + (uint32_t)(nt * 8 * 64));
#pragma unroll
                for (int mt = 0; mt < 4; ++mt)
                    mma_bf16(d[mt][nt], af[mt], bh0, bh1);
            }
        }
        __syncthreads();
        if (c + 2 < NCH) load_stage(c + 2, s);
    }

    // epilogue: add bias, write fp32
#pragma unroll
    for (int nt = 0; nt < 4; ++nt) {
        const int col = n0 + wn * 32 + nt * 8 + tig * 2;
        const float2 bv = *(const float2*)(bias + col);
#pragma unroll
        for (int mt = 0; mt < 4; ++mt) {
            const int row = m0 + wm * 64 + mt * 16 + g;
            float2 v0 = make_float2(d[mt][nt][0] + bv.x, d[mt][nt][1] + bv.y);
            float2 v1 = make_float2(d[mt][nt][2] + bv.x, d[mt][nt][3] + bv.y);
            *(float2*)(C + (size_t)row * N + col)       = v0;
            *(float2*)(C + (size_t)(row + 8) * N + col) = v1;
        }
    }
}

// ===================== banded causal attention (fp32) =======================
// row i attends to cols [i-W, i]; one thread per query; K/V streamed via smem.
// Warp-level clamp: warp covering queries [qw,qw+31] only iterates keys in
// [qw-W, qw+31] within each chunk (256 -> ~160 key iters).
// Writes output directly as bf16 hi/lo split for the second GEMM.
__global__ void __launch_bounds__(128)
attn_kernel(const float* __restrict__ qkv,
            __nv_bfloat16* __restrict__ ohi, __nv_bfloat16* __restrict__ olo)
{
    __shared__ __align__(16) float Ks[64][HDn];
    __shared__ __align__(16) float Vs[64][HDn];

    const int qtile = blockIdx.x;
    const int h     = blockIdx.y;
    const int b     = blockIdx.z;
    const int qbase = qtile * 128;
    const int gq    = qbase + threadIdx.x;
    const int qw    = qbase + (threadIdx.x & ~31);   // warp's first query
    const int kstart = (qbase - Wn) > 0 ? (qbase - Wn) : 0;
    const int span   = qbase + 128 - kstart;
    const float scale = 0.125f;

    f32x2_t q2[32];
    {
        const f32x2_t* qp = (const f32x2_t*)(qkv + (size_t)(b * Sn + gq) * (3 * En) + h * HDn);
#pragma unroll
        for (int i = 0; i < 32; i++) q2[i] = qp[i];
    }

    f32x2_t acc2[32];
#pragma unroll
    for (int i = 0; i < 32; i++) acc2[i] = 0ULL;
    float m = -3.0e38f, l = 0.0f;

    for (int c0 = 0; c0 < span; c0 += 64) {
        const int nk = (span - c0) < 64 ? (span - c0) : 64;
        __syncthreads();
        for (int idx = threadIdx.x; idx < 64 * 16; idx += 128) {
            int r = idx >> 4, c4 = (idx & 15) << 2;
            if (r < nk) {
                const float* src =
                    qkv + (size_t)(b * Sn + kstart + c0 + r) * (3 * En) + h * HDn + c4;
                *(float4*)&Ks[r][c4] = *(const float4*)(src + En);
                *(float4*)&Vs[r][c4] = *(const float4*)(src + 2 * En);
            }
        }
        __syncthreads();

        // warp-uniform clamp of key range within this chunk
        const int cbase = kstart + c0;
        int jlo = qw - Wn - cbase; if (jlo < 0) jlo = 0;
        int jhi = qw + 31 - cbase; if (jhi > nk - 1) jhi = nk - 1;

        for (int j = jlo; j <= jhi; ++j) {
            const f32x2_t* kp = (const f32x2_t*)&Ks[j][0];
            f32x2_t s0 = 0ULL, s1 = 0ULL, s2 = 0ULL, s3 = 0ULL;
#pragma unroll
            for (int i = 0; i < 32; i += 4) {
                s0 = ffma2(q2[i + 0], kp[i + 0], s0);
                s1 = ffma2(q2[i + 1], kp[i + 1], s1);
                s2 = ffma2(q2[i + 2], kp[i + 2], s2);
                s3 = ffma2(q2[i + 3], kp[i + 3], s3);
            }
            s0 = fadd2(fadd2(s0, s1), fadd2(s2, s3));
            float slo, shi; unpack2(s0, slo, shi);
            float s = (slo + shi) * scale;

            const int gj = cbase + j;
            if (gj <= gq && gj >= gq - Wn) {
                const f32x2_t* vp = (const f32x2_t*)&Vs[j][0];
                if (s <= m) {
                    float p = __expf(s - m);
                    l += p;
                    f32x2_t p2 = pack2(p, p);
#pragma unroll
                    for (int i = 0; i < 32; i++) acc2[i] = ffma2(p2, vp[i], acc2[i]);
                } else {
                    float corr = __expf(m - s);
                    m = s;
                    l = l * corr + 1.0f;
                    f32x2_t c2v = pack2(corr, corr);
#pragma unroll
                    for (int i = 0; i < 32; i++) acc2[i] = ffma2(acc2[i], c2v, vp[i]);
                }
            }
        }
    }

    const float inv = 1.0f / l;
    const size_t rb = (size_t)(b * Sn + gq) * En + h * HDn;
    uint32_t* hp = (uint32_t*)(ohi + rb);
    uint32_t* lp = (uint32_t*)(olo + rb);
#pragma unroll
    for (int i = 0; i < 32; i++) {
        float v0, v1; unpack2(acc2[i], v0, v1);
        v0 *= inv; v1 *= inv;
        __nv_bfloat16 h0 = __float2bfloat16_rn(v0), h1 = __float2bfloat16_rn(v1);
        __nv_bfloat16 l0 = __float2bfloat16_rn(v0 - __bfloat162float(h0));
        __nv_bfloat16 l1 = __float2bfloat16_rn(v1 - __bfloat162float(h1));
        hp[i] = ((uint32_t)__bfloat16_as_ushort(h1) << 16) | __bfloat16_as_ushort(h0);
        lp[i] = ((uint32_t)__bfloat16_as_ushort(l1) << 16) | __bfloat16_as_ushort(l0);
    }
}

// ---------------------------------------------------------------------------
extern "C" void kernel_launch(void* const* d_in, const int* in_sizes, int n_in,
                              void* d_out, int out_size)
{
    const float *x = 0, *w_in = 0, *b_in = 0, *w_out = 0, *b_out = 0;
    for (int i = 0; i < n_in; i++) {
        const float* p = (const float*)d_in[i];
        switch (in_sizes[i]) {
            case Bn * Sn * En: x     = p; break;
            case 3 * En * En:  w_in  = p; break;
            case 3 * En:       b_in  = p; break;
            case En * En:      w_out = p; break;
            case En:           b_out = p; break;
            default: break;
        }
    }

    void *p_qkv, *p_xhi, *p_xlo, *p_winhi, *p_winlo, *p_wouthi, *p_woutlo, *p_ahi, *p_alo;
    cudaGetSymbolAddress(&p_qkv, g_qkv);
    cudaGetSymbolAddress(&p_xhi, g_xhi);     cudaGetSymbolAddress(&p_xlo, g_xlo);
    cudaGetSymbolAddress(&p_winhi, g_winhi); cudaGetSymbolAddress(&p_winlo, g_winlo);
    cudaGetSymbolAddress(&p_wouthi, g_wouthi); cudaGetSymbolAddress(&p_woutlo, g_woutlo);
    cudaGetSymbolAddress(&p_ahi, g_ahi);     cudaGetSymbolAddress(&p_alo, g_alo);

    cudaFuncSetAttribute(gemm_bf16split, cudaFuncAttributeMaxDynamicSharedMemorySize, GEMM_SMEM);
    cudaFuncSetAttribute(gemm_bf16split, cudaFuncAttributePreferredSharedMemoryCarveout, 100);

    // fp32 -> bf16 hi/lo splits
    conv_hilo<<<8192, 256>>>((const float4*)x,
                             (uint2*)p_xhi, (uint2*)p_xlo, (Bn * Sn * En) / 4);
    conv_hilo<<<3072, 256>>>((const float4*)w_in,
                             (uint2*)p_winhi, (uint2*)p_winlo, (3 * En * En) / 4);
    conv_hilo<<<1024, 256>>>((const float4*)w_out,
                             (uint2*)p_wouthi, (uint2*)p_woutlo, (En * En) / 4);

    // 1) QKV projection: [8192,1024] x [3072,1024]^T -> fp32 qkv
    {
        dim3 g((3 * En) / NT, (Bn * Sn) / MT);   // 24 x 64
        gemm_bf16split<<<g, 256, GEMM_SMEM>>>(
            (const __nv_bfloat16*)p_xhi, (const __nv_bfloat16*)p_xlo,
            (const __nv_bfloat16*)p_winhi, (const __nv_bfloat16*)p_winlo,
            b_in, (float*)p_qkv, 3 * En);
    }

    // 2) banded attention (fp32 in, bf16 hi/lo out)
    {
        dim3 g(Sn / 128, Hn, Bn);
        attn_kernel<<<g, 128>>>((const float*)p_qkv,
                                (__nv_bfloat16*)p_ahi, (__nv_bfloat16*)p_alo);
    }

    // 3) output projection: [8192,1024] x [1024,1024]^T -> d_out
    {
        dim3 g(En / NT, (Bn * Sn) / MT);         // 8 x 64
        gemm_bf16split<<<g, 256, GEMM_SMEM>>>(
            (const __nv_bfloat16*)p_ahi, (const __nv_bfloat16*)p_alo,
            (const __nv_bfloat16*)p_wouthi, (const __nv_bfloat16*)p_woutlo,
            b_out, (float*)d_out, En);
    }
}